// round 1
// baseline (speedup 1.0000x reference)
#include <cuda_runtime.h>
#include <cuda_bf16.h>
#include <math.h>

// ---------------- problem constants ----------------
#define BB 4
#define TT 784          // patches
#define GG 28
#define EE 768
#define HDIM 3072
#define NHEADS 12
#define DHEAD 64
#define NLAYERS 6
#define MM (BB*TT)      // 3136 tokens total

// ---------------- scratch (global device arrays; no allocation) ----------------
__device__ float g_xp[MM * EE];            // patch matrix
__device__ float g_h[MM * EE];             // residual stream
__device__ float g_y[MM * EE];             // LN output
__device__ float g_qkv[MM * 3 * EE];       // qkv
__device__ float g_scores[(size_t)BB * NHEADS * TT * TT]; // 118MB
__device__ float g_o[MM * EE];             // attention output
__device__ float g_mlp[MM * HDIM];         // mlp hidden

// epilogue modes
#define EPI_NONE 0
#define EPI_POS  1
#define EPI_RES  2
#define EPI_GELU 3

// ---------------- patch gather ----------------
__global__ void patch_gather(const float* __restrict__ x, float* __restrict__ xp) {
    int idx = blockIdx.x * 256 + threadIdx.x;
    if (idx >= MM * EE) return;
    int j = idx % EE;
    int m = idx / EE;
    int b = m / TT, t = m % TT;
    int gr = t / GG, gc = t % GG;
    int ch = j >> 8;          // j / 256
    int pr = (j >> 4) & 15;
    int pc = j & 15;
    xp[idx] = x[(((size_t)b * 448 + gr * 16 + pr) * 448 + (gc * 16 + pc)) * 3 + ch];
}

// ---------------- generic C[M,N] = A[M,K] @ W[N,K]^T + bias, with epilogue ----------------
// requires M%64==0, N%64==0, K%16==0
__global__ void gemm_nt(const float* __restrict__ A, const float* __restrict__ W,
                        const float* __restrict__ bias, const float* __restrict__ extra,
                        float* __restrict__ C, int M, int N, int K, int epi)
{
    __shared__ float As[16][68];
    __shared__ float Ws[16][68];
    int tx = threadIdx.x, ty = threadIdx.y;
    int tid = ty * 16 + tx;
    int m0 = blockIdx.y * 64, n0 = blockIdx.x * 64;
    float acc[4][4] = {};

    for (int k0 = 0; k0 < K; k0 += 16) {
        #pragma unroll
        for (int i = 0; i < 4; i++) {
            int idx = tid + i * 256;
            int r = idx >> 4, c = idx & 15;
            As[c][r] = A[(size_t)(m0 + r) * K + k0 + c];
            Ws[c][r] = W[(size_t)(n0 + r) * K + k0 + c];
        }
        __syncthreads();
        #pragma unroll
        for (int k = 0; k < 16; k++) {
            float4 a = *reinterpret_cast<const float4*>(&As[k][ty * 4]);
            float4 b = *reinterpret_cast<const float4*>(&Ws[k][tx * 4]);
            float av[4] = {a.x, a.y, a.z, a.w};
            float bv[4] = {b.x, b.y, b.z, b.w};
            #pragma unroll
            for (int i = 0; i < 4; i++)
                #pragma unroll
                for (int j = 0; j < 4; j++)
                    acc[i][j] += av[i] * bv[j];
        }
        __syncthreads();
    }

    #pragma unroll
    for (int i = 0; i < 4; i++) {
        int m = m0 + ty * 4 + i;
        #pragma unroll
        for (int j = 0; j < 4; j++) {
            int n = n0 + tx * 4 + j;
            float v = acc[i][j] + bias[n];
            if (epi == EPI_POS)  v += extra[(size_t)(m % TT) * N + n];
            else if (epi == EPI_RES) v += extra[(size_t)m * N + n];
            else if (epi == EPI_GELU) v = 0.5f * v * (1.0f + erff(v * 0.70710678118654752f));
            C[(size_t)m * N + n] = v;
        }
    }
}

// ---------------- attention scores: s = q.k/8 + local mask ----------------
__global__ void attn_scores(const float* __restrict__ qkv, float* __restrict__ scores)
{
    int bh = blockIdx.z;
    int b = bh / NHEADS, h = bh % NHEADS;
    int q0 = blockIdx.y * 64, k0 = blockIdx.x * 64;
    __shared__ float Qs[16][68];
    __shared__ float Ks[16][68];
    int tx = threadIdx.x, ty = threadIdx.y;
    int tid = ty * 16 + tx;
    const float* qbase = qkv + (size_t)b * TT * (3 * EE) + h * DHEAD;
    const float* kbase = qbase + EE;
    float acc[4][4] = {};

    for (int d0 = 0; d0 < DHEAD; d0 += 16) {
        #pragma unroll
        for (int i = 0; i < 4; i++) {
            int idx = tid + i * 256;
            int r = idx >> 4, c = idx & 15;
            int qt = q0 + r;
            Qs[c][r] = (qt < TT) ? qbase[(size_t)qt * (3 * EE) + d0 + c] : 0.f;
            int kt = k0 + r;
            Ks[c][r] = (kt < TT) ? kbase[(size_t)kt * (3 * EE) + d0 + c] : 0.f;
        }
        __syncthreads();
        #pragma unroll
        for (int k = 0; k < 16; k++) {
            float4 a = *reinterpret_cast<const float4*>(&Qs[k][ty * 4]);
            float4 bq = *reinterpret_cast<const float4*>(&Ks[k][tx * 4]);
            float av[4] = {a.x, a.y, a.z, a.w};
            float bv[4] = {bq.x, bq.y, bq.z, bq.w};
            #pragma unroll
            for (int i = 0; i < 4; i++)
                #pragma unroll
                for (int j = 0; j < 4; j++)
                    acc[i][j] += av[i] * bv[j];
        }
        __syncthreads();
    }

    #pragma unroll
    for (int i = 0; i < 4; i++) {
        int q = q0 + ty * 4 + i;
        if (q >= TT) continue;
        int rq = q / GG, cq = q - rq * GG;
        #pragma unroll
        for (int j = 0; j < 4; j++) {
            int k = k0 + tx * 4 + j;
            if (k >= TT) continue;
            int rk = k / GG, ck = k - rk * GG;
            float s = acc[i][j] * 0.125f;   // 1/sqrt(64)
            if (abs(rq - rk) <= 4 && abs(cq - ck) <= 4) s = -1e30f; // local masked OUT
            scores[((size_t)bh * TT + q) * TT + k] = s;
        }
    }
}

// ---------------- row softmax over 784 ----------------
__global__ void softmax_rows(float* __restrict__ scores)
{
    int q = blockIdx.x;
    int bh = blockIdx.y;
    float* p = scores + ((size_t)bh * TT + q) * TT;
    __shared__ float red[256];
    int tid = threadIdx.x;

    float mx = -1e30f;
    for (int i = tid; i < TT; i += 256) mx = fmaxf(mx, p[i]);
    red[tid] = mx; __syncthreads();
    for (int st = 128; st > 0; st >>= 1) {
        if (tid < st) red[tid] = fmaxf(red[tid], red[tid + st]);
        __syncthreads();
    }
    mx = red[0]; __syncthreads();

    float sum = 0.f;
    for (int i = tid; i < TT; i += 256) {
        float e = __expf(p[i] - mx);
        p[i] = e;
        sum += e;
    }
    red[tid] = sum; __syncthreads();
    for (int st = 128; st > 0; st >>= 1) {
        if (tid < st) red[tid] += red[tid + st];
        __syncthreads();
    }
    float inv = 1.0f / red[0];
    for (int i = tid; i < TT; i += 256) p[i] *= inv;
}

// ---------------- o = a @ v ----------------
__global__ void attn_av(const float* __restrict__ scores, const float* __restrict__ qkv,
                        float* __restrict__ o)
{
    int bh = blockIdx.y;
    int b = bh / NHEADS, h = bh % NHEADS;
    int q0 = blockIdx.x * 64;
    __shared__ float Ss[16][68];
    __shared__ float Vs[16][68];
    int tx = threadIdx.x, ty = threadIdx.y;
    int tid = ty * 16 + tx;
    const float* srow = scores + (size_t)bh * TT * TT;
    const float* vbase = qkv + (size_t)b * TT * (3 * EE) + 2 * EE + h * DHEAD;
    float acc[4][4] = {};

    for (int k0 = 0; k0 < TT; k0 += 16) {
        #pragma unroll
        for (int i = 0; i < 4; i++) {
            int idx = tid + i * 256;
            // S tile: 64 q-rows x 16 k-cols, stored transposed Ss[k][q]
            int r = idx >> 4, c = idx & 15;
            int q = q0 + r;
            Ss[c][r] = (q < TT) ? srow[(size_t)q * TT + k0 + c] : 0.f;
            // V tile: 16 k-rows x 64 d-cols
            int kr = idx >> 6, dc = idx & 63;
            Vs[kr][dc] = vbase[(size_t)(k0 + kr) * (3 * EE) + dc];
        }
        __syncthreads();
        #pragma unroll
        for (int kk = 0; kk < 16; kk++) {
            float4 a = *reinterpret_cast<const float4*>(&Ss[kk][ty * 4]);
            float4 v = *reinterpret_cast<const float4*>(&Vs[kk][tx * 4]);
            float av[4] = {a.x, a.y, a.z, a.w};
            float vv[4] = {v.x, v.y, v.z, v.w};
            #pragma unroll
            for (int i = 0; i < 4; i++)
                #pragma unroll
                for (int j = 0; j < 4; j++)
                    acc[i][j] += av[i] * vv[j];
        }
        __syncthreads();
    }

    #pragma unroll
    for (int i = 0; i < 4; i++) {
        int q = q0 + ty * 4 + i;
        if (q >= TT) continue;
        #pragma unroll
        for (int j = 0; j < 4; j++) {
            int d = tx * 4 + j;
            o[((size_t)(b * TT + q)) * EE + h * DHEAD + d] = acc[i][j];
        }
    }
}

// ---------------- layernorm (block per token) ----------------
__global__ void ln_kernel(const float* __restrict__ x, const float* __restrict__ g,
                          const float* __restrict__ bp, float* __restrict__ y)
{
    int m = blockIdx.x;
    const float* xr = x + (size_t)m * EE;
    float* yr = y + (size_t)m * EE;
    __shared__ float red[256];
    int tid = threadIdx.x;

    float s = 0.f;
    for (int i = tid; i < EE; i += 256) s += xr[i];
    red[tid] = s; __syncthreads();
    for (int st = 128; st > 0; st >>= 1) { if (tid < st) red[tid] += red[tid + st]; __syncthreads(); }
    float mean = red[0] / EE; __syncthreads();

    float v = 0.f;
    for (int i = tid; i < EE; i += 256) { float d = xr[i] - mean; v += d * d; }
    red[tid] = v; __syncthreads();
    for (int st = 128; st > 0; st >>= 1) { if (tid < st) red[tid] += red[tid + st]; __syncthreads(); }
    float inv = rsqrtf(red[0] / EE + 1e-5f);

    for (int i = tid; i < EE; i += 256)
        yr[i] = (xr[i] - mean) * inv * g[i] + bp[i];
}

// ---------------- head: LN + linear(E->1) + flux, writes patch_flux ----------------
__global__ void head_kernel(const float* __restrict__ hbuf,
                            const float* __restrict__ lnw, const float* __restrict__ lnb,
                            const float* __restrict__ hw, const float* __restrict__ hb,
                            const float* __restrict__ mean_s, const float* __restrict__ std_s,
                            float* __restrict__ out)
{
    int m = blockIdx.x;
    const float* xr = hbuf + (size_t)m * EE;
    __shared__ float red[256];
    int tid = threadIdx.x;

    float s = 0.f;
    for (int i = tid; i < EE; i += 256) s += xr[i];
    red[tid] = s; __syncthreads();
    for (int st = 128; st > 0; st >>= 1) { if (tid < st) red[tid] += red[tid + st]; __syncthreads(); }
    float mean = red[0] / EE; __syncthreads();

    float v = 0.f;
    for (int i = tid; i < EE; i += 256) { float d = xr[i] - mean; v += d * d; }
    red[tid] = v; __syncthreads();
    for (int st = 128; st > 0; st >>= 1) { if (tid < st) red[tid] += red[tid + st]; __syncthreads(); }
    float inv = rsqrtf(red[0] / EE + 1e-5f); __syncthreads();

    float dot = 0.f;
    for (int i = tid; i < EE; i += 256)
        dot += ((xr[i] - mean) * inv * lnw[i] + lnb[i]) * hw[i];
    red[tid] = dot; __syncthreads();
    for (int st = 128; st > 0; st >>= 1) { if (tid < st) red[tid] += red[tid + st]; __syncthreads(); }

    if (tid == 0) {
        float logit = red[0] + hb[0];
        float lg = logit * std_s[0] + mean_s[0];
        float pf = exp10f(lg) - 1e-8f;
        pf = fminf(fmaxf(pf, 1e-15f), 1.0f);
        out[BB + m] = pf;   // patch_flux after the B global values
    }
}

// ---------------- global flux sum per batch ----------------
__global__ void flux_reduce(float* __restrict__ out)
{
    int b = blockIdx.x;
    __shared__ float red[256];
    int tid = threadIdx.x;
    float s = 0.f;
    for (int i = tid; i < TT; i += 256) s += out[BB + b * TT + i];
    red[tid] = s; __syncthreads();
    for (int st = 128; st > 0; st >>= 1) { if (tid < st) red[tid] += red[tid + st]; __syncthreads(); }
    if (tid == 0) out[b] = fmaxf(red[0], 1e-15f);
}

// ---------------- launcher ----------------
extern "C" void kernel_launch(void* const* d_in, const int* in_sizes, int n_in,
                              void* d_out, int out_size)
{
    const float* x        = (const float*)d_in[0];
    const float* sxr_mean = (const float*)d_in[1];
    const float* sxr_std  = (const float*)d_in[2];
    const float* input_w  = (const float*)d_in[3];
    const float* input_b  = (const float*)d_in[4];
    const float* pos_emb  = (const float*)d_in[5];
    const float* ln1_w    = (const float*)d_in[6];
    const float* ln1_b    = (const float*)d_in[7];
    const float* in_w     = (const float*)d_in[8];
    const float* in_b     = (const float*)d_in[9];
    const float* out_w    = (const float*)d_in[10];
    const float* out_b    = (const float*)d_in[11];
    const float* ln2_w    = (const float*)d_in[12];
    const float* ln2_b    = (const float*)d_in[13];
    const float* w1       = (const float*)d_in[14];
    const float* b1       = (const float*)d_in[15];
    const float* w2       = (const float*)d_in[16];
    const float* b2       = (const float*)d_in[17];
    const float* head_lnw = (const float*)d_in[18];
    const float* head_lnb = (const float*)d_in[19];
    const float* head_w   = (const float*)d_in[20];
    const float* head_b   = (const float*)d_in[21];
    float* out = (float*)d_out;

    float *xp, *h, *y, *qkv, *scores, *o, *mlp;
    cudaGetSymbolAddress((void**)&xp,     g_xp);
    cudaGetSymbolAddress((void**)&h,      g_h);
    cudaGetSymbolAddress((void**)&y,      g_y);
    cudaGetSymbolAddress((void**)&qkv,    g_qkv);
    cudaGetSymbolAddress((void**)&scores, g_scores);
    cudaGetSymbolAddress((void**)&o,      g_o);
    cudaGetSymbolAddress((void**)&mlp,    g_mlp);

    dim3 blk2(16, 16);

    // patch embedding
    patch_gather<<<(MM * EE + 255) / 256, 256>>>(x, xp);
    gemm_nt<<<dim3(EE / 64, MM / 64), blk2>>>(xp, input_w, input_b, pos_emb, h,
                                              MM, EE, EE, EPI_POS);

    for (int l = 0; l < NLAYERS; l++) {
        const float* l1w = ln1_w + (size_t)l * EE;
        const float* l1b = ln1_b + (size_t)l * EE;
        const float* iw  = in_w  + (size_t)l * 3 * EE * EE;
        const float* ib  = in_b  + (size_t)l * 3 * EE;
        const float* ow  = out_w + (size_t)l * EE * EE;
        const float* ob  = out_b + (size_t)l * EE;
        const float* l2w = ln2_w + (size_t)l * EE;
        const float* l2b = ln2_b + (size_t)l * EE;
        const float* W1  = w1 + (size_t)l * HDIM * EE;
        const float* B1  = b1 + (size_t)l * HDIM;
        const float* W2  = w2 + (size_t)l * EE * HDIM;
        const float* B2  = b2 + (size_t)l * EE;

        ln_kernel<<<MM, 256>>>(h, l1w, l1b, y);
        gemm_nt<<<dim3(3 * EE / 64, MM / 64), blk2>>>(y, iw, ib, nullptr, qkv,
                                                      MM, 3 * EE, EE, EPI_NONE);
        attn_scores<<<dim3(13, 13, BB * NHEADS), blk2>>>(qkv, scores);
        softmax_rows<<<dim3(TT, BB * NHEADS), 256>>>(scores);
        attn_av<<<dim3(13, BB * NHEADS), blk2>>>(scores, qkv, o);
        gemm_nt<<<dim3(EE / 64, MM / 64), blk2>>>(o, ow, ob, h, h,
                                                  MM, EE, EE, EPI_RES);
        ln_kernel<<<MM, 256>>>(h, l2w, l2b, y);
        gemm_nt<<<dim3(HDIM / 64, MM / 64), blk2>>>(y, W1, B1, nullptr, mlp,
                                                    MM, HDIM, EE, EPI_GELU);
        gemm_nt<<<dim3(EE / 64, MM / 64), blk2>>>(mlp, W2, B2, h, h,
                                                  MM, EE, HDIM, EPI_RES);
    }

    head_kernel<<<MM, 256>>>(h, head_lnw, head_lnb, head_w, head_b,
                             sxr_mean, sxr_std, out);
    flux_reduce<<<BB, 256>>>(out);
}

// round 2
// speedup vs baseline: 1.2012x; 1.2012x over previous
#include <cuda_runtime.h>
#include <cuda_bf16.h>
#include <math.h>
#include <stdint.h>

// ---------------- problem constants ----------------
#define BB 4
#define TT 784          // patches
#define GG 28
#define EE 768
#define HDIM 3072
#define NHEADS 12
#define DHEAD 64
#define NLAYERS 6
#define MM (BB*TT)      // 3136 tokens total
#define MPAD 3200       // padded to 25*128 for clean 128-row tiles

// ---------------- scratch (global device arrays; no allocation) ----------------
__device__ float g_xp[MPAD * EE];          // patch matrix (pad rows stay 0 forever)
__device__ float g_h[MPAD * EE];           // residual stream
__device__ float g_y[MPAD * EE];           // LN output
__device__ float g_qkv[MPAD * 3 * EE];     // qkv
__device__ float g_scores[(size_t)BB * NHEADS * TT * TT]; // 118MB
__device__ float g_o[MPAD * EE];           // attention output
__device__ float g_mlp[MPAD * HDIM];       // mlp hidden

// epilogue modes
#define EPI_NONE 0
#define EPI_POS  1
#define EPI_RES  2
#define EPI_GELU 3

// ---------------- tf32 helpers ----------------
__device__ __forceinline__ uint32_t f2tf32(float f) {
    uint32_t u;
    asm("cvt.rna.tf32.f32 %0, %1;" : "=r"(u) : "f"(f));
    return u;
}

__device__ __forceinline__ void mma_tf32(float d[4], const uint32_t a[4],
                                         uint32_t b0, uint32_t b1) {
    asm volatile(
        "mma.sync.aligned.m16n8k8.row.col.f32.tf32.tf32.f32 "
        "{%0,%1,%2,%3}, {%4,%5,%6,%7}, {%8,%9}, {%0,%1,%2,%3};"
        : "+f"(d[0]), "+f"(d[1]), "+f"(d[2]), "+f"(d[3])
        : "r"(a[0]), "r"(a[1]), "r"(a[2]), "r"(a[3]), "r"(b0), "r"(b1));
}

// ---------------- patch gather ----------------
__global__ void patch_gather(const float* __restrict__ x, float* __restrict__ xp) {
    int idx = blockIdx.x * 256 + threadIdx.x;
    if (idx >= MM * EE) return;
    int j = idx % EE;
    int m = idx / EE;
    int b = m / TT, t = m % TT;
    int gr = t / GG, gc = t % GG;
    int ch = j >> 8;          // j / 256
    int pr = (j >> 4) & 15;
    int pc = j & 15;
    xp[idx] = x[(((size_t)b * 448 + gr * 16 + pr) * 448 + (gc * 16 + pc)) * 3 + ch];
}

// ---------------- 3xTF32 tensor-core GEMM ----------------
// C[M,N] = A[M,K] @ W[N,K]^T + bias, with epilogue.
// M % 128 == 0 (we pad to MPAD), N % 128 == 0, K % 16 == 0.
// Block tile 128x128, 256 threads = 8 warps, warp tile 32x64.
// hi/lo split of fp32 into two tf32 values; 3 MMA passes (hi*hi, hi*lo, lo*hi)
// give ~fp32 accuracy.
__global__ __launch_bounds__(256, 2)
void gemm_tf32(const float* __restrict__ A, const float* __restrict__ W,
               const float* __restrict__ bias, const float* __restrict__ extra,
               float* __restrict__ C, int M, int N, int K, int epi)
{
    // smem layout: [row][16 k-cols permuted], pad to 18 for conflict reduction.
    __shared__ float Ah[128][18];
    __shared__ float Al[128][18];
    __shared__ float Wh[128][18];
    __shared__ float Wl[128][18];

    int tid  = threadIdx.x;
    int warp = tid >> 5;
    int lane = tid & 31;
    int r  = lane >> 2;   // 0..7
    int cq = lane & 3;    // 0..3

    int m0 = blockIdx.y * 128;
    int n0 = blockIdx.x * 128;
    int warp_m = (warp & 3) * 32;
    int warp_n = (warp >> 2) * 64;

    float acc[2][8][4] = {};

    int ldrow  = tid >> 1;        // 0..127
    int ldhalf = tid & 1;         // 0..1 (8 floats each)

    const int KITERS = K >> 4;
    for (int kc = 0; kc < KITERS; kc++) {
        int k0 = kc << 4;

        // ---- load A tile (128x16) and W tile (128x16), split hi/lo, permute k ----
        {
            const float4* pA = reinterpret_cast<const float4*>(
                A + (size_t)(m0 + ldrow) * K + k0 + ldhalf * 8);
            const float4* pW = reinterpret_cast<const float4*>(
                W + (size_t)(n0 + ldrow) * K + k0 + ldhalf * 8);
            #pragma unroll
            for (int v = 0; v < 2; v++) {
                float4 fa = pA[v];
                float4 fw = pW[v];
                float va[4] = {fa.x, fa.y, fa.z, fa.w};
                float vw[4] = {fw.x, fw.y, fw.z, fw.w};
                #pragma unroll
                for (int e = 0; e < 4; e++) {
                    int c  = ldhalf * 8 + v * 4 + e;        // 0..15
                    int s  = c >> 3, cc = c & 7;
                    int p  = (s << 3) | ((cc & 3) << 1) | (cc >> 2); // pair-permuted
                    float a  = va[e];
                    float ah = __uint_as_float(f2tf32(a));
                    Ah[ldrow][p] = ah;
                    Al[ldrow][p] = __uint_as_float(f2tf32(a - ah));
                    float w  = vw[e];
                    float wh = __uint_as_float(f2tf32(w));
                    Wh[ldrow][p] = wh;
                    Wl[ldrow][p] = __uint_as_float(f2tf32(w - wh));
                }
            }
        }
        __syncthreads();

        // ---- MMA over the two k8 sub-steps ----
        #pragma unroll
        for (int s = 0; s < 2; s++) {
            uint32_t ah[2][4], al[2][4];
            #pragma unroll
            for (int i2 = 0; i2 < 2; i2++) {
                int mr = warp_m + 16 * i2 + r;
                uint2 h0 = *reinterpret_cast<const uint2*>(&Ah[mr][8 * s + 2 * cq]);
                uint2 h1 = *reinterpret_cast<const uint2*>(&Ah[mr + 8][8 * s + 2 * cq]);
                ah[i2][0] = h0.x; ah[i2][1] = h1.x; ah[i2][2] = h0.y; ah[i2][3] = h1.y;
                uint2 l0 = *reinterpret_cast<const uint2*>(&Al[mr][8 * s + 2 * cq]);
                uint2 l1 = *reinterpret_cast<const uint2*>(&Al[mr + 8][8 * s + 2 * cq]);
                al[i2][0] = l0.x; al[i2][1] = l1.x; al[i2][2] = l0.y; al[i2][3] = l1.y;
            }
            #pragma unroll
            for (int j = 0; j < 8; j++) {
                int nr = warp_n + 8 * j + r;
                uint2 bh = *reinterpret_cast<const uint2*>(&Wh[nr][8 * s + 2 * cq]);
                uint2 bl = *reinterpret_cast<const uint2*>(&Wl[nr][8 * s + 2 * cq]);
                #pragma unroll
                for (int i2 = 0; i2 < 2; i2++) {
                    mma_tf32(acc[i2][j], ah[i2], bl.x, bl.y);   // hi*lo
                    mma_tf32(acc[i2][j], al[i2], bh.x, bh.y);   // lo*hi
                    mma_tf32(acc[i2][j], ah[i2], bh.x, bh.y);   // hi*hi
                }
            }
        }
        __syncthreads();
    }

    // ---- epilogue ----
    #pragma unroll
    for (int i2 = 0; i2 < 2; i2++) {
        int row0 = m0 + warp_m + 16 * i2 + r;
        #pragma unroll
        for (int j = 0; j < 8; j++) {
            int col = n0 + warp_n + 8 * j + 2 * cq;
            #pragma unroll
            for (int half = 0; half < 2; half++) {      // half 0: rows r, half 1: rows r+8
                int m = row0 + half * 8;
                #pragma unroll
                for (int e = 0; e < 2; e++) {
                    int n = col + e;
                    float v = acc[i2][j][half * 2 + e] + bias[n];
                    if (epi == EPI_POS)       v += extra[(size_t)(m % TT) * N + n];
                    else if (epi == EPI_RES)  v += extra[(size_t)m * N + n];
                    else if (epi == EPI_GELU) v = 0.5f * v * (1.0f + erff(v * 0.70710678118654752f));
                    C[(size_t)m * N + n] = v;
                }
            }
        }
    }
}

// ---------------- attention scores: s = q.k/8 + local mask ----------------
__global__ void attn_scores(const float* __restrict__ qkv, float* __restrict__ scores)
{
    int bh = blockIdx.z;
    int b = bh / NHEADS, h = bh % NHEADS;
    int q0 = blockIdx.y * 64, k0 = blockIdx.x * 64;
    __shared__ float Qs[16][68];
    __shared__ float Ks[16][68];
    int tx = threadIdx.x, ty = threadIdx.y;
    int tid = ty * 16 + tx;
    const float* qbase = qkv + (size_t)b * TT * (3 * EE) + h * DHEAD;
    const float* kbase = qbase + EE;
    float acc[4][4] = {};

    for (int d0 = 0; d0 < DHEAD; d0 += 16) {
        #pragma unroll
        for (int i = 0; i < 4; i++) {
            int idx = tid + i * 256;
            int rr = idx >> 4, c = idx & 15;
            int qt = q0 + rr;
            Qs[c][rr] = (qt < TT) ? qbase[(size_t)qt * (3 * EE) + d0 + c] : 0.f;
            int kt = k0 + rr;
            Ks[c][rr] = (kt < TT) ? kbase[(size_t)kt * (3 * EE) + d0 + c] : 0.f;
        }
        __syncthreads();
        #pragma unroll
        for (int k = 0; k < 16; k++) {
            float4 a = *reinterpret_cast<const float4*>(&Qs[k][ty * 4]);
            float4 bq = *reinterpret_cast<const float4*>(&Ks[k][tx * 4]);
            float av[4] = {a.x, a.y, a.z, a.w};
            float bv[4] = {bq.x, bq.y, bq.z, bq.w};
            #pragma unroll
            for (int i = 0; i < 4; i++)
                #pragma unroll
                for (int j = 0; j < 4; j++)
                    acc[i][j] += av[i] * bv[j];
        }
        __syncthreads();
    }

    #pragma unroll
    for (int i = 0; i < 4; i++) {
        int q = q0 + ty * 4 + i;
        if (q >= TT) continue;
        int rq = q / GG, cq2 = q - rq * GG;
        #pragma unroll
        for (int j = 0; j < 4; j++) {
            int k = k0 + tx * 4 + j;
            if (k >= TT) continue;
            int rk = k / GG, ck = k - rk * GG;
            float s = acc[i][j] * 0.125f;   // 1/sqrt(64)
            if (abs(rq - rk) <= 4 && abs(cq2 - ck) <= 4) s = -1e30f; // local masked OUT
            scores[((size_t)bh * TT + q) * TT + k] = s;
        }
    }
}

// ---------------- row softmax over 784 ----------------
__global__ void softmax_rows(float* __restrict__ scores)
{
    int q = blockIdx.x;
    int bh = blockIdx.y;
    float* p = scores + ((size_t)bh * TT + q) * TT;
    __shared__ float red[256];
    int tid = threadIdx.x;

    float mx = -1e30f;
    for (int i = tid; i < TT; i += 256) mx = fmaxf(mx, p[i]);
    red[tid] = mx; __syncthreads();
    for (int st = 128; st > 0; st >>= 1) {
        if (tid < st) red[tid] = fmaxf(red[tid], red[tid + st]);
        __syncthreads();
    }
    mx = red[0]; __syncthreads();

    float sum = 0.f;
    for (int i = tid; i < TT; i += 256) {
        float e = __expf(p[i] - mx);
        p[i] = e;
        sum += e;
    }
    red[tid] = sum; __syncthreads();
    for (int st = 128; st > 0; st >>= 1) {
        if (tid < st) red[tid] += red[tid + st];
        __syncthreads();
    }
    float inv = 1.0f / red[0];
    for (int i = tid; i < TT; i += 256) p[i] *= inv;
}

// ---------------- o = a @ v ----------------
__global__ void attn_av(const float* __restrict__ scores, const float* __restrict__ qkv,
                        float* __restrict__ o)
{
    int bh = blockIdx.y;
    int b = bh / NHEADS, h = bh % NHEADS;
    int q0 = blockIdx.x * 64;
    __shared__ float Ss[16][68];
    __shared__ float Vs[16][68];
    int tx = threadIdx.x, ty = threadIdx.y;
    int tid = ty * 16 + tx;
    const float* srow = scores + (size_t)bh * TT * TT;
    const float* vbase = qkv + (size_t)b * TT * (3 * EE) + 2 * EE + h * DHEAD;
    float acc[4][4] = {};

    for (int k0 = 0; k0 < TT; k0 += 16) {
        #pragma unroll
        for (int i = 0; i < 4; i++) {
            int idx = tid + i * 256;
            int rr = idx >> 4, c = idx & 15;
            int q = q0 + rr;
            Ss[c][rr] = (q < TT) ? srow[(size_t)q * TT + k0 + c] : 0.f;
            int kr = idx >> 6, dc = idx & 63;
            Vs[kr][dc] = vbase[(size_t)(k0 + kr) * (3 * EE) + dc];
        }
        __syncthreads();
        #pragma unroll
        for (int kk = 0; kk < 16; kk++) {
            float4 a = *reinterpret_cast<const float4*>(&Ss[kk][ty * 4]);
            float4 v = *reinterpret_cast<const float4*>(&Vs[kk][tx * 4]);
            float av[4] = {a.x, a.y, a.z, a.w};
            float vv[4] = {v.x, v.y, v.z, v.w};
            #pragma unroll
            for (int i = 0; i < 4; i++)
                #pragma unroll
                for (int j = 0; j < 4; j++)
                    acc[i][j] += av[i] * vv[j];
        }
        __syncthreads();
    }

    #pragma unroll
    for (int i = 0; i < 4; i++) {
        int q = q0 + ty * 4 + i;
        if (q >= TT) continue;
        #pragma unroll
        for (int j = 0; j < 4; j++) {
            int d = tx * 4 + j;
            o[((size_t)(b * TT + q)) * EE + h * DHEAD + d] = acc[i][j];
        }
    }
}

// ---------------- layernorm (block per token) ----------------
__global__ void ln_kernel(const float* __restrict__ x, const float* __restrict__ g,
                          const float* __restrict__ bp, float* __restrict__ y)
{
    int m = blockIdx.x;
    const float* xr = x + (size_t)m * EE;
    float* yr = y + (size_t)m * EE;
    __shared__ float red[256];
    int tid = threadIdx.x;

    float s = 0.f;
    for (int i = tid; i < EE; i += 256) s += xr[i];
    red[tid] = s; __syncthreads();
    for (int st = 128; st > 0; st >>= 1) { if (tid < st) red[tid] += red[tid + st]; __syncthreads(); }
    float mean = red[0] / EE; __syncthreads();

    float v = 0.f;
    for (int i = tid; i < EE; i += 256) { float d = xr[i] - mean; v += d * d; }
    red[tid] = v; __syncthreads();
    for (int st = 128; st > 0; st >>= 1) { if (tid < st) red[tid] += red[tid + st]; __syncthreads(); }
    float inv = rsqrtf(red[0] / EE + 1e-5f);

    for (int i = tid; i < EE; i += 256)
        yr[i] = (xr[i] - mean) * inv * g[i] + bp[i];
}

// ---------------- head: LN + linear(E->1) + flux, writes patch_flux ----------------
__global__ void head_kernel(const float* __restrict__ hbuf,
                            const float* __restrict__ lnw, const float* __restrict__ lnb,
                            const float* __restrict__ hw, const float* __restrict__ hb,
                            const float* __restrict__ mean_s, const float* __restrict__ std_s,
                            float* __restrict__ out)
{
    int m = blockIdx.x;
    const float* xr = hbuf + (size_t)m * EE;
    __shared__ float red[256];
    int tid = threadIdx.x;

    float s = 0.f;
    for (int i = tid; i < EE; i += 256) s += xr[i];
    red[tid] = s; __syncthreads();
    for (int st = 128; st > 0; st >>= 1) { if (tid < st) red[tid] += red[tid + st]; __syncthreads(); }
    float mean = red[0] / EE; __syncthreads();

    float v = 0.f;
    for (int i = tid; i < EE; i += 256) { float d = xr[i] - mean; v += d * d; }
    red[tid] = v; __syncthreads();
    for (int st = 128; st > 0; st >>= 1) { if (tid < st) red[tid] += red[tid + st]; __syncthreads(); }
    float inv = rsqrtf(red[0] / EE + 1e-5f); __syncthreads();

    float dot = 0.f;
    for (int i = tid; i < EE; i += 256)
        dot += ((xr[i] - mean) * inv * lnw[i] + lnb[i]) * hw[i];
    red[tid] = dot; __syncthreads();
    for (int st = 128; st > 0; st >>= 1) { if (tid < st) red[tid] += red[tid + st]; __syncthreads(); }

    if (tid == 0) {
        float logit = red[0] + hb[0];
        float lg = logit * std_s[0] + mean_s[0];
        float pf = exp10f(lg) - 1e-8f;
        pf = fminf(fmaxf(pf, 1e-15f), 1.0f);
        out[BB + m] = pf;   // patch_flux after the B global values
    }
}

// ---------------- global flux sum per batch ----------------
__global__ void flux_reduce(float* __restrict__ out)
{
    int b = blockIdx.x;
    __shared__ float red[256];
    int tid = threadIdx.x;
    float s = 0.f;
    for (int i = tid; i < TT; i += 256) s += out[BB + b * TT + i];
    red[tid] = s; __syncthreads();
    for (int st = 128; st > 0; st >>= 1) { if (tid < st) red[tid] += red[tid + st]; __syncthreads(); }
    if (tid == 0) out[b] = fmaxf(red[0], 1e-15f);
}

// ---------------- launcher ----------------
extern "C" void kernel_launch(void* const* d_in, const int* in_sizes, int n_in,
                              void* d_out, int out_size)
{
    const float* x        = (const float*)d_in[0];
    const float* sxr_mean = (const float*)d_in[1];
    const float* sxr_std  = (const float*)d_in[2];
    const float* input_w  = (const float*)d_in[3];
    const float* input_b  = (const float*)d_in[4];
    const float* pos_emb  = (const float*)d_in[5];
    const float* ln1_w    = (const float*)d_in[6];
    const float* ln1_b    = (const float*)d_in[7];
    const float* in_w     = (const float*)d_in[8];
    const float* in_b     = (const float*)d_in[9];
    const float* out_w    = (const float*)d_in[10];
    const float* out_b    = (const float*)d_in[11];
    const float* ln2_w    = (const float*)d_in[12];
    const float* ln2_b    = (const float*)d_in[13];
    const float* w1       = (const float*)d_in[14];
    const float* b1       = (const float*)d_in[15];
    const float* w2       = (const float*)d_in[16];
    const float* b2       = (const float*)d_in[17];
    const float* head_lnw = (const float*)d_in[18];
    const float* head_lnb = (const float*)d_in[19];
    const float* head_w   = (const float*)d_in[20];
    const float* head_b   = (const float*)d_in[21];
    float* out = (float*)d_out;

    float *xp, *h, *y, *qkv, *scores, *o, *mlp;
    cudaGetSymbolAddress((void**)&xp,     g_xp);
    cudaGetSymbolAddress((void**)&h,      g_h);
    cudaGetSymbolAddress((void**)&y,      g_y);
    cudaGetSymbolAddress((void**)&qkv,    g_qkv);
    cudaGetSymbolAddress((void**)&scores, g_scores);
    cudaGetSymbolAddress((void**)&o,      g_o);
    cudaGetSymbolAddress((void**)&mlp,    g_mlp);

    dim3 blk2(16, 16);

    // patch embedding (pad rows of xp are never written: they are 0 from module
    // load, so GEMM pad-row outputs are deterministic)
    patch_gather<<<(MM * EE + 255) / 256, 256>>>(x, xp);
    gemm_tf32<<<dim3(EE / 128, MPAD / 128), 256>>>(xp, input_w, input_b, pos_emb, h,
                                                   MPAD, EE, EE, EPI_POS);

    for (int l = 0; l < NLAYERS; l++) {
        const float* l1w = ln1_w + (size_t)l * EE;
        const float* l1b = ln1_b + (size_t)l * EE;
        const float* iw  = in_w  + (size_t)l * 3 * EE * EE;
        const float* ib  = in_b  + (size_t)l * 3 * EE;
        const float* ow  = out_w + (size_t)l * EE * EE;
        const float* ob  = out_b + (size_t)l * EE;
        const float* l2w = ln2_w + (size_t)l * EE;
        const float* l2b = ln2_b + (size_t)l * EE;
        const float* W1  = w1 + (size_t)l * HDIM * EE;
        const float* B1  = b1 + (size_t)l * HDIM;
        const float* W2  = w2 + (size_t)l * EE * HDIM;
        const float* B2  = b2 + (size_t)l * EE;

        ln_kernel<<<MM, 256>>>(h, l1w, l1b, y);
        gemm_tf32<<<dim3(3 * EE / 128, MPAD / 128), 256>>>(y, iw, ib, nullptr, qkv,
                                                           MPAD, 3 * EE, EE, EPI_NONE);
        attn_scores<<<dim3(13, 13, BB * NHEADS), blk2>>>(qkv, scores);
        softmax_rows<<<dim3(TT, BB * NHEADS), 256>>>(scores);
        attn_av<<<dim3(13, BB * NHEADS), blk2>>>(scores, qkv, o);
        gemm_tf32<<<dim3(EE / 128, MPAD / 128), 256>>>(o, ow, ob, h, h,
                                                       MPAD, EE, EE, EPI_RES);
        ln_kernel<<<MM, 256>>>(h, l2w, l2b, y);
        gemm_tf32<<<dim3(HDIM / 128, MPAD / 128), 256>>>(y, W1, B1, nullptr, mlp,
                                                         MPAD, HDIM, EE, EPI_GELU);
        gemm_tf32<<<dim3(EE / 128, MPAD / 128), 256>>>(mlp, W2, B2, h, h,
                                                       MPAD, EE, HDIM, EPI_RES);
    }

    head_kernel<<<MM, 256>>>(h, head_lnw, head_lnb, head_w, head_b,
                             sxr_mean, sxr_std, out);
    flux_reduce<<<BB, 256>>>(out);
}